// round 12
// baseline (speedup 1.0000x reference)
#include <cuda_runtime.h>
#include <cuda_fp16.h>
#include <cstdint>

#define HIDDEN 64
#define BATCH  4096
#define TSTEPS 9
#define DIM    512
#define GDIM   256                 // 4*HIDDEN
#define MROWS  (BATCH * TSTEPS)    // 36864

// Scratch (static device globals: allocation-guard-safe)
__device__ float  g_xg[(size_t)MROWS * GDIM];   // xg = x @ Wx + bias
__device__ __half g_wxTh[(size_t)GDIM * DIM];   // Wx^T [256][512] in fp16

// ---------------------------------------------------------------------------
// helpers
// ---------------------------------------------------------------------------
__device__ __forceinline__ void mma_f16(float c[4],
                                        unsigned a0, unsigned a1, unsigned a2, unsigned a3,
                                        unsigned b0, unsigned b1) {
    asm volatile(
        "mma.sync.aligned.m16n8k16.row.col.f32.f16.f16.f32 "
        "{%0,%1,%2,%3}, {%4,%5,%6,%7}, {%8,%9}, {%0,%1,%2,%3};"
        : "+f"(c[0]), "+f"(c[1]), "+f"(c[2]), "+f"(c[3])
        : "r"(a0), "r"(a1), "r"(a2), "r"(a3), "r"(b0), "r"(b1));
}

__device__ __forceinline__ unsigned pack_h2(float lo, float hi) {
    unsigned r;   // cvt.rn.f16x2.f32 d,a,b : a -> high half, b -> low half
    asm("cvt.rn.f16x2.f32 %0, %1, %2;" : "=r"(r) : "f"(hi), "f"(lo));
    return r;
}

__device__ __forceinline__ float sigm(float x)  { return 1.0f / (1.0f + __expf(-x)); }
__device__ __forceinline__ float tanhx(float x) { return 1.0f - 2.0f / (__expf(2.0f * x) + 1.0f); }
__device__ __forceinline__ void fma2(unsigned long long& acc,
                                     unsigned long long a, unsigned long long b) {
    asm("fma.rn.f32x2 %0, %1, %2, %0;" : "+l"(acc) : "l"(a), "l"(b));
}
__device__ __forceinline__ unsigned long long pack64(float lo, float hi) {
    unsigned long long r;
    asm("mov.b64 %0, {%1,%2};" : "=l"(r) : "f"(lo), "f"(hi));
    return r;
}
__device__ __forceinline__ unsigned long long dup64(float v) {
    unsigned long long r;
    asm("mov.b64 %0, {%1,%1};" : "=l"(r) : "f"(v));
    return r;
}

// ---------------------------------------------------------------------------
// Kernel 0: Wx^T in fp16:  g_wxTh[n][k] = half(Wx[k][n])
// ---------------------------------------------------------------------------
__global__ void wtrans(const float* __restrict__ w) {
    const int idx = blockIdx.x * 256 + threadIdx.x;   // over 256*512
    const int n = idx >> 9, k = idx & 511;
    g_wxTh[idx] = __float2half(w[(size_t)k * GDIM + n]);
}

// ---------------------------------------------------------------------------
// Kernel 1: xg[36864,256] = x @ Wx + bias  (fp16 mma m16n8k16, fp32 accum)
// BM=128, BN=256, BK=32. 512 threads = 16 warps (4m x 4n), warp tile 32x64.
// DOUBLE-buffered smem: one __syncthreads per K-tile; LDG prefetch hides
// under COMPUTE; STS of tile k+1 overlaps other warps' MMA tails.
// ---------------------------------------------------------------------------
#define BMg 128
#define BNg 256
#define BKg 32
#define KST 20                                   // half2 stride per row
#define STAGE ((BMg + BNg) * KST)                // 7680 unsigned per stage
#define GEMM_SMEM (2 * STAGE * 4)                // 61440 B

__global__ void __launch_bounds__(512, 1)
gemm_xg(const float* __restrict__ x, const float* __restrict__ bias) {
    extern __shared__ unsigned sm[];

    const int tid = threadIdx.x;
    const int bm  = blockIdx.x * BMg;
    const int wid = tid >> 5, lane = tid & 31;
    const int wm = wid & 3, wn = wid >> 2;
    const int grp = lane >> 2, tig = lane & 3;

    // staging coords
    const int ra = tid >> 2, ca = (tid & 3) * 8;   // A: 8 floats / thread
    const int rb = tid >> 1, cb = (tid & 1) * 8;   // B: 8 half2 (16 halves) / thread

    const float* asrc = x + (size_t)(bm + ra) * DIM + ca;
    const __half* bsrc = g_wxTh + (size_t)rb * DIM + cb * 2;

    float4 av0, av1;
    uint4  bv0, bv1;

    auto LOAD = [&](int kt) {
        av0 = *(const float4*)(asrc + kt * BKg);
        av1 = *(const float4*)(asrc + kt * BKg + 4);
        bv0 = *(const uint4*)(bsrc + kt * BKg);       // halves 0..7
        bv1 = *(const uint4*)(bsrc + kt * BKg + 8);   // halves 8..15
    };
    auto STORE = [&](int s) {
        unsigned* As2 = sm + s * STAGE;
        unsigned* Bs2 = As2 + BMg * KST;
        uint4 ah;
        ah.x = pack_h2(av0.x, av0.y);
        ah.y = pack_h2(av0.z, av0.w);
        ah.z = pack_h2(av1.x, av1.y);
        ah.w = pack_h2(av1.z, av1.w);
        *(uint4*)(As2 + ra * KST + ca / 2)   = ah;
        *(uint4*)(Bs2 + rb * KST + cb)       = bv0;
        *(uint4*)(Bs2 + rb * KST + cb + 4)   = bv1;
    };

    float acc[2][8][4];
    #pragma unroll
    for (int i = 0; i < 2; i++)
        #pragma unroll
        for (int j = 0; j < 8; j++)
            #pragma unroll
            for (int k = 0; k < 4; k++) acc[i][j][k] = 0.0f;

    auto COMPUTE = [&](int s) {
        const unsigned* As2 = sm + s * STAGE;
        const unsigned* Bs2 = As2 + BMg * KST;
        #pragma unroll
        for (int ks = 0; ks < 2; ks++) {
            const int kb = ks * 8;
            unsigned af[2][4];
            #pragma unroll
            for (int mi = 0; mi < 2; mi++) {
                const int r0 = wm * 32 + mi * 16;
                af[mi][0] = As2[(r0 + grp) * KST + kb + tig];
                af[mi][1] = As2[(r0 + grp + 8) * KST + kb + tig];
                af[mi][2] = As2[(r0 + grp) * KST + kb + tig + 4];
                af[mi][3] = As2[(r0 + grp + 8) * KST + kb + tig + 4];
            }
            #pragma unroll
            for (int ni = 0; ni < 8; ni++) {
                const int c0 = wn * 64 + ni * 8;
                unsigned b0 = Bs2[(c0 + grp) * KST + kb + tig];
                unsigned b1 = Bs2[(c0 + grp) * KST + kb + tig + 4];
                #pragma unroll
                for (int mi = 0; mi < 2; mi++)
                    mma_f16(acc[mi][ni], af[mi][0], af[mi][1], af[mi][2], af[mi][3], b0, b1);
            }
        }
    };

    LOAD(0);
    STORE(0);
    __syncthreads();
    #pragma unroll 1
    for (int kt = 1; kt < DIM / BKg; kt++) {
        LOAD(kt);                    // prefetch: latency hides under COMPUTE
        COMPUTE((kt - 1) & 1);
        STORE(kt & 1);               // safe: that buffer last read in iter kt-1
        __syncthreads();             // single barrier per K-tile
    }
    COMPUTE(1);                      // (DIM/BKg - 1) & 1 == 1

    // epilogue: natural layout xg[row][col] + bias
    #pragma unroll
    for (int mi = 0; mi < 2; mi++) {
        #pragma unroll
        for (int ni = 0; ni < 8; ni++) {
            const int row = bm + wm * 32 + mi * 16 + grp;
            const int col = wn * 64 + ni * 8 + tig * 2;
            const float bb0 = bias[col], bb1 = bias[col + 1];
            g_xg[(size_t)row * GDIM + col]           = acc[mi][ni][0] + bb0;
            g_xg[(size_t)row * GDIM + col + 1]       = acc[mi][ni][1] + bb1;
            g_xg[(size_t)(row + 8) * GDIM + col]     = acc[mi][ni][2] + bb0;
            g_xg[(size_t)(row + 8) * GDIM + col + 1] = acc[mi][ni][3] + bb1;
        }
    }
}

// ---------------------------------------------------------------------------
// Kernel 2: LSTM scan — BATCH-PACKED f32x2 FFMA2.
// FFMA2 lanes = two batches (not two gates): one LDS.128 weight quad
// (4 gates for this h) + 4 broadcast LDS.64 h-pairs feed 16 FFMA2
// -> crossbar cost per FFMA2 halves vs gate-packing. {w,w} dup is an ALU
// mov.b64 (parallel pipe). CTA = 128 threads (h=tid&63, bq=tid>>6),
// 16 batches/CTA, 256 CTAs, smem 73 KB -> 3 CTAs/SM.
// t=0 skips the k-loop (h0 = 0).
// ---------------------------------------------------------------------------
#define SCB 16                   // batches per CTA
#define HVS 9                    // 64-bit units per k-row (8 pairs + pad)
#define SCAN_SMEM (64 * 256 * 4 + 2 * 64 * HVS * 8)   // 74752 B

__global__ void __launch_bounds__(128, 3)
lstm_scan(const float* __restrict__ w, float* __restrict__ out) {
    extern __shared__ float sms[];
    float* Whr = sms;                                                // [64][256]
    unsigned long long* hvv = (unsigned long long*)(sms + 64 * 256); // [2][64][HVS]

    const int tid   = threadIdx.x;
    const int h     = tid & 63;
    const int bq    = tid >> 6;                    // 0..1
    const int bbase = blockIdx.x * SCB + bq * 8;   // 8 batches / thread

    // load + permute Wh: Whr[k][h*4+q] = Wh[k][q*64+h]
    for (int idx = tid; idx < 64 * 256; idx += 128) {
        const int k = idx >> 8, col = idx & 255;
        const int q = col >> 6, hh = col & 63;
        Whr[k * 256 + hh * 4 + q] = w[(size_t)(DIM + k) * GDIM + col];
    }
    __syncthreads();

    float c[8];
    #pragma unroll
    for (int j = 0; j < 8; j++) c[j] = 0.0f;

    unsigned long long acc[4][4];     // [gate][batch-pair]

    for (int t = 0; t < TSTEPS; t++) {
        // gates = xg, packed {batch 2p, batch 2p+1} per gate
        #pragma unroll
        for (int p = 0; p < 4; p++) {
            const size_t r0 = ((size_t)(bbase + 2 * p) * TSTEPS + t) * GDIM + h;
            const size_t r1 = ((size_t)(bbase + 2 * p + 1) * TSTEPS + t) * GDIM + h;
            #pragma unroll
            for (int g = 0; g < 4; g++)
                acc[g][p] = pack64(g_xg[r0 + g * 64], g_xg[r1 + g * 64]);
        }

        if (t > 0) {
            const unsigned long long* hp =
                hvv + ((t - 1) & 1) * 64 * HVS + bq * 4;
            #pragma unroll 4
            for (int k = 0; k < 64; k++) {
                const float4 wq = *(const float4*)(Whr + k * 256 + h * 4);  // LDS.128
                const unsigned long long wd0 = dup64(wq.x);
                const unsigned long long wd1 = dup64(wq.y);
                const unsigned long long wd2 = dup64(wq.z);
                const unsigned long long wd3 = dup64(wq.w);
                #pragma unroll
                for (int p = 0; p < 4; p++) {
                    const unsigned long long hk = hp[k * HVS + p];  // bcast {h0,h1}
                    fma2(acc[0][p], wd0, hk);
                    fma2(acc[1][p], wd1, hk);
                    fma2(acc[2][p], wd2, hk);
                    fma2(acc[3][p], wd3, hk);
                }
            }
        }

        // activations + state update; write {hn0,hn1} pair for next step
        unsigned long long* hw = hvv + (t & 1) * 64 * HVS + h * HVS + bq * 4;
        #pragma unroll
        for (int p = 0; p < 4; p++) {
            float i0, i1, j0, j1, f0, f1, o0, o1;
            asm("mov.b64 {%0,%1}, %2;" : "=f"(i0), "=f"(i1) : "l"(acc[0][p]));
            asm("mov.b64 {%0,%1}, %2;" : "=f"(j0), "=f"(j1) : "l"(acc[1][p]));
            asm("mov.b64 {%0,%1}, %2;" : "=f"(f0), "=f"(f1) : "l"(acc[2][p]));
            asm("mov.b64 {%0,%1}, %2;" : "=f"(o0), "=f"(o1) : "l"(acc[3][p]));

            const float cn0 = sigm(f0 + 1.0f) * c[2 * p]     + sigm(i0) * tanhx(j0);
            const float cn1 = sigm(f1 + 1.0f) * c[2 * p + 1] + sigm(i1) * tanhx(j1);
            c[2 * p]     = cn0;
            c[2 * p + 1] = cn1;
            const float hn0 = sigm(o0) * tanhx(cn0);
            const float hn1 = sigm(o1) * tanhx(cn1);

            hw[p] = pack64(hn0, hn1);
            out[((size_t)(bbase + 2 * p) * TSTEPS + t) * HIDDEN + h]     = hn0;
            out[((size_t)(bbase + 2 * p + 1) * TSTEPS + t) * HIDDEN + h] = hn1;
        }
        __syncthreads();
    }
}

// ---------------------------------------------------------------------------
extern "C" void kernel_launch(void* const* d_in, const int* in_sizes, int n_in,
                              void* d_out, int out_size) {
    const float* x    = (const float*)d_in[0];
    const float* w    = (const float*)d_in[1];
    const float* bias = (const float*)d_in[2];
    float* out        = (float*)d_out;
    (void)in_sizes; (void)n_in; (void)out_size;

    wtrans<<<GDIM * DIM / 256, 256>>>(w);

    cudaFuncSetAttribute(gemm_xg, cudaFuncAttributeMaxDynamicSharedMemorySize, GEMM_SMEM);
    gemm_xg<<<MROWS / BMg, 512, GEMM_SMEM>>>(x, bias);

    cudaFuncSetAttribute(lstm_scan, cudaFuncAttributeMaxDynamicSharedMemorySize, SCAN_SMEM);
    lstm_scan<<<BATCH / SCB, 128, SCAN_SMEM>>>(w, out);
}

// round 13
// speedup vs baseline: 1.0328x; 1.0328x over previous
#include <cuda_runtime.h>
#include <cuda_fp16.h>
#include <cstdint>

#define HIDDEN 64
#define BATCH  4096
#define TSTEPS 9
#define DIM    512
#define GDIM   256                 // 4*HIDDEN
#define MROWS  (BATCH * TSTEPS)    // 36864

// Scratch (static device globals: allocation-guard-safe)
__device__ float  g_xg[(size_t)MROWS * GDIM];   // xg = x @ Wx + bias
__device__ __half g_wxTh[(size_t)GDIM * DIM];   // Wx^T [256][512] in fp16

// ---------------------------------------------------------------------------
// helpers
// ---------------------------------------------------------------------------
__device__ __forceinline__ void mma_f16(float c[4],
                                        unsigned a0, unsigned a1, unsigned a2, unsigned a3,
                                        unsigned b0, unsigned b1) {
    asm volatile(
        "mma.sync.aligned.m16n8k16.row.col.f32.f16.f16.f32 "
        "{%0,%1,%2,%3}, {%4,%5,%6,%7}, {%8,%9}, {%0,%1,%2,%3};"
        : "+f"(c[0]), "+f"(c[1]), "+f"(c[2]), "+f"(c[3])
        : "r"(a0), "r"(a1), "r"(a2), "r"(a3), "r"(b0), "r"(b1));
}

__device__ __forceinline__ unsigned pack_h2(float lo, float hi) {
    unsigned r;   // cvt.rn.f16x2.f32 d,a,b : a -> high half, b -> low half
    asm("cvt.rn.f16x2.f32 %0, %1, %2;" : "=r"(r) : "f"(hi), "f"(lo));
    return r;
}

__device__ __forceinline__ float sigm(float x)  { return 1.0f / (1.0f + __expf(-x)); }
__device__ __forceinline__ float tanhx(float x) { return 1.0f - 2.0f / (__expf(2.0f * x) + 1.0f); }
__device__ __forceinline__ void fma2(unsigned long long& acc,
                                     unsigned long long a, unsigned long long b) {
    asm("fma.rn.f32x2 %0, %1, %2, %0;" : "+l"(acc) : "l"(a), "l"(b));
}

// ---------------------------------------------------------------------------
// Kernel 0: Wx^T in fp16:  g_wxTh[n][k] = half(Wx[k][n])
// ---------------------------------------------------------------------------
__global__ void wtrans(const float* __restrict__ w) {
    const int idx = blockIdx.x * 256 + threadIdx.x;   // over 256*512
    const int n = idx >> 9, k = idx & 511;
    g_wxTh[idx] = __float2half(w[(size_t)k * GDIM + n]);
}

// ---------------------------------------------------------------------------
// Kernel 1: xg[36864,256] = x @ Wx + bias  (fp16 mma m16n8k16, fp32 accum)
// BM=128, BN=256, BK=32. 512 threads = 16 warps (4m x 4n), warp tile 32x64.
// DOUBLE-buffered smem: one __syncthreads per K-tile; LDG prefetch hides
// under COMPUTE; STS of tile k+1 overlaps other warps' MMA tails.
// ---------------------------------------------------------------------------
#define BMg 128
#define BNg 256
#define BKg 32
#define KST 20                                   // half2 stride per row
#define STAGE ((BMg + BNg) * KST)                // 7680 unsigned per stage
#define GEMM_SMEM (2 * STAGE * 4)                // 61440 B

__global__ void __launch_bounds__(512, 1)
gemm_xg(const float* __restrict__ x, const float* __restrict__ bias) {
    extern __shared__ unsigned sm[];

    const int tid = threadIdx.x;
    const int bm  = blockIdx.x * BMg;
    const int wid = tid >> 5, lane = tid & 31;
    const int wm = wid & 3, wn = wid >> 2;
    const int grp = lane >> 2, tig = lane & 3;

    // staging coords
    const int ra = tid >> 2, ca = (tid & 3) * 8;   // A: 8 floats / thread
    const int rb = tid >> 1, cb = (tid & 1) * 8;   // B: 8 half2 (16 halves) / thread

    const float* asrc = x + (size_t)(bm + ra) * DIM + ca;
    const __half* bsrc = g_wxTh + (size_t)rb * DIM + cb * 2;

    float4 av0, av1;
    uint4  bv0, bv1;

    auto LOAD = [&](int kt) {
        av0 = *(const float4*)(asrc + kt * BKg);
        av1 = *(const float4*)(asrc + kt * BKg + 4);
        bv0 = *(const uint4*)(bsrc + kt * BKg);       // halves 0..7
        bv1 = *(const uint4*)(bsrc + kt * BKg + 8);   // halves 8..15
    };
    auto STORE = [&](int s) {
        unsigned* As2 = sm + s * STAGE;
        unsigned* Bs2 = As2 + BMg * KST;
        uint4 ah;
        ah.x = pack_h2(av0.x, av0.y);
        ah.y = pack_h2(av0.z, av0.w);
        ah.z = pack_h2(av1.x, av1.y);
        ah.w = pack_h2(av1.z, av1.w);
        *(uint4*)(As2 + ra * KST + ca / 2)   = ah;
        *(uint4*)(Bs2 + rb * KST + cb)       = bv0;
        *(uint4*)(Bs2 + rb * KST + cb + 4)   = bv1;
    };

    float acc[2][8][4];
    #pragma unroll
    for (int i = 0; i < 2; i++)
        #pragma unroll
        for (int j = 0; j < 8; j++)
            #pragma unroll
            for (int k = 0; k < 4; k++) acc[i][j][k] = 0.0f;

    auto COMPUTE = [&](int s) {
        const unsigned* As2 = sm + s * STAGE;
        const unsigned* Bs2 = As2 + BMg * KST;
        #pragma unroll
        for (int ks = 0; ks < 2; ks++) {
            const int kb = ks * 8;
            unsigned af[2][4];
            #pragma unroll
            for (int mi = 0; mi < 2; mi++) {
                const int r0 = wm * 32 + mi * 16;
                af[mi][0] = As2[(r0 + grp) * KST + kb + tig];
                af[mi][1] = As2[(r0 + grp + 8) * KST + kb + tig];
                af[mi][2] = As2[(r0 + grp) * KST + kb + tig + 4];
                af[mi][3] = As2[(r0 + grp + 8) * KST + kb + tig + 4];
            }
            #pragma unroll
            for (int ni = 0; ni < 8; ni++) {
                const int c0 = wn * 64 + ni * 8;
                unsigned b0 = Bs2[(c0 + grp) * KST + kb + tig];
                unsigned b1 = Bs2[(c0 + grp) * KST + kb + tig + 4];
                #pragma unroll
                for (int mi = 0; mi < 2; mi++)
                    mma_f16(acc[mi][ni], af[mi][0], af[mi][1], af[mi][2], af[mi][3], b0, b1);
            }
        }
    };

    LOAD(0);
    STORE(0);
    __syncthreads();
    #pragma unroll 1
    for (int kt = 1; kt < DIM / BKg; kt++) {
        LOAD(kt);                    // prefetch: latency hides under COMPUTE
        COMPUTE((kt - 1) & 1);
        STORE(kt & 1);               // safe: last read in iter kt-1, pre-barrier
        __syncthreads();             // single barrier per K-tile
    }
    COMPUTE(1);                      // (DIM/BKg - 1) & 1 == 1

    // epilogue: natural layout xg[row][col] + bias
    #pragma unroll
    for (int mi = 0; mi < 2; mi++) {
        #pragma unroll
        for (int ni = 0; ni < 8; ni++) {
            const int row = bm + wm * 32 + mi * 16 + grp;
            const int col = wn * 64 + ni * 8 + tig * 2;
            const float bb0 = bias[col], bb1 = bias[col + 1];
            g_xg[(size_t)row * GDIM + col]           = acc[mi][ni][0] + bb0;
            g_xg[(size_t)row * GDIM + col + 1]       = acc[mi][ni][1] + bb1;
            g_xg[(size_t)(row + 8) * GDIM + col]     = acc[mi][ni][2] + bb0;
            g_xg[(size_t)(row + 8) * GDIM + col + 1] = acc[mi][ni][3] + bb1;
        }
    }
}

// ---------------------------------------------------------------------------
// Kernel 2: LSTM scan — round-9 measured-good structure (gate-packed FFMA2).
// 256 CTAs x 16 batches, 256 threads (4 batches/thread), smem 83 KB ->
// 2 CTAs/SM (16 warps). Thread (h=tid&63, bq=tid>>6) owns gate quad
// {i,j,f,o}[h] for 4 batches; gates packed (i,j)/(f,o); h stored duplicated
// {h,h} so one LDS.64 broadcast feeds both FFMA2s with no dup movs in the
// hot loop. t=0 skips the k-loop (h0 = 0).
// ---------------------------------------------------------------------------
#define NBATCH 16
#define HV 17                    // 64-bit stride per hidden row (odd)
#define SCAN_SMEM (64 * 256 * 4 + 2 * 64 * HV * 8)   // 82944 B

__global__ void __launch_bounds__(256, 2)
lstm_scan(const float* __restrict__ w, float* __restrict__ out) {
    extern __shared__ float sms[];
    float* Whr = sms;                                                // [64][256]
    unsigned long long* hvv = (unsigned long long*)(sms + 64 * 256); // [2][64][HV]

    const int tid   = threadIdx.x;
    const int h     = tid & 63;
    const int bq    = tid >> 6;                    // 0..3
    const int bbase = blockIdx.x * NBATCH + bq * 4;

    // load + permute Wh: Whr[k][h*4+q] = Wh[k][q*64+h]
    for (int idx = tid; idx < 64 * 256; idx += 256) {
        const int k = idx >> 8, col = idx & 255;
        const int q = col >> 6, hh = col & 63;
        Whr[k * 256 + hh * 4 + q] = w[(size_t)(DIM + k) * GDIM + col];
    }
    __syncthreads();

    float c[4];
    #pragma unroll
    for (int j = 0; j < 4; j++) c[j] = 0.0f;

    unsigned long long acc01[4], acc23[4];

    for (int t = 0; t < TSTEPS; t++) {
        #pragma unroll
        for (int j = 0; j < 4; j++) {
            const size_t ro = ((size_t)(bbase + j) * TSTEPS + t) * GDIM;
            const float gi = g_xg[ro + h];
            const float gj = g_xg[ro + 64 + h];
            const float gf = g_xg[ro + 128 + h];
            const float go = g_xg[ro + 192 + h];
            asm("mov.b64 %0, {%1,%2};" : "=l"(acc01[j]) : "f"(gi), "f"(gj));
            asm("mov.b64 %0, {%1,%2};" : "=l"(acc23[j]) : "f"(gf), "f"(go));
        }

        if (t > 0) {
            const unsigned long long* hp = hvv + ((t - 1) & 1) * 64 * HV + bq * 4;
            #pragma unroll 4
            for (int k = 0; k < 64; k++) {
                const ulonglong2 wv = *(const ulonglong2*)(Whr + k * 256 + h * 4);
                #pragma unroll
                for (int j = 0; j < 4; j++) {
                    const unsigned long long hk = hp[k * HV + j];   // bcast {h,h}
                    fma2(acc01[j], wv.x, hk);
                    fma2(acc23[j], wv.y, hk);
                }
            }
        }

        unsigned long long* hw = hvv + (t & 1) * 64 * HV + h * HV + bq * 4;
        #pragma unroll
        for (int j = 0; j < 4; j++) {
            float gi, gj, gf, go;
            asm("mov.b64 {%0,%1}, %2;" : "=f"(gi), "=f"(gj) : "l"(acc01[j]));
            asm("mov.b64 {%0,%1}, %2;" : "=f"(gf), "=f"(go) : "l"(acc23[j]));
            const float ig = sigm(gi);
            const float jg = tanhx(gj);
            const float fg = sigm(gf + 1.0f);          // FORGET_BIAS
            const float og = sigm(go);
            const float cn = fg * c[j] + ig * jg;
            c[j] = cn;
            const float hn = og * tanhx(cn);
            unsigned long long hd;
            asm("mov.b64 %0, {%1,%1};" : "=l"(hd) : "f"(hn));
            hw[j] = hd;
            out[((size_t)(bbase + j) * TSTEPS + t) * HIDDEN + h] = hn;
        }
        __syncthreads();
    }
}

// ---------------------------------------------------------------------------
extern "C" void kernel_launch(void* const* d_in, const int* in_sizes, int n_in,
                              void* d_out, int out_size) {
    const float* x    = (const float*)d_in[0];
    const float* w    = (const float*)d_in[1];
    const float* bias = (const float*)d_in[2];
    float* out        = (float*)d_out;
    (void)in_sizes; (void)n_in; (void)out_size;

    wtrans<<<GDIM * DIM / 256, 256>>>(w);

    cudaFuncSetAttribute(gemm_xg, cudaFuncAttributeMaxDynamicSharedMemorySize, GEMM_SMEM);
    gemm_xg<<<MROWS / BMg, 512, GEMM_SMEM>>>(x, bias);

    cudaFuncSetAttribute(lstm_scan, cudaFuncAttributeMaxDynamicSharedMemorySize, SCAN_SMEM);
    lstm_scan<<<BATCH / NBATCH, 256, SCAN_SMEM>>>(w, out);
}

// round 14
// speedup vs baseline: 1.3347x; 1.2923x over previous
#include <cuda_runtime.h>
#include <cuda_fp16.h>
#include <cstdint>

#define HIDDEN 64
#define BATCH  4096
#define TSTEPS 9
#define DIM    512
#define GDIM   256                 // 4*HIDDEN
#define MROWS  (BATCH * TSTEPS)    // 36864

// Scratch (static device globals: allocation-guard-safe)
__device__ float  g_xg[(size_t)MROWS * GDIM];   // xg = x @ Wx + bias
__device__ __half g_wxTh[(size_t)GDIM * DIM];   // Wx^T [256][512] in fp16

// ---------------------------------------------------------------------------
// helpers
// ---------------------------------------------------------------------------
__device__ __forceinline__ void mma_f16(float c[4],
                                        unsigned a0, unsigned a1, unsigned a2, unsigned a3,
                                        unsigned b0, unsigned b1) {
    asm volatile(
        "mma.sync.aligned.m16n8k16.row.col.f32.f16.f16.f32 "
        "{%0,%1,%2,%3}, {%4,%5,%6,%7}, {%8,%9}, {%0,%1,%2,%3};"
        : "+f"(c[0]), "+f"(c[1]), "+f"(c[2]), "+f"(c[3])
        : "r"(a0), "r"(a1), "r"(a2), "r"(a3), "r"(b0), "r"(b1));
}

__device__ __forceinline__ unsigned pack_h2(float lo, float hi) {
    unsigned r;   // cvt.rn.f16x2.f32 d,a,b : a -> high half, b -> low half
    asm("cvt.rn.f16x2.f32 %0, %1, %2;" : "=r"(r) : "f"(hi), "f"(lo));
    return r;
}

__device__ __forceinline__ float sigm(float x)  { return 1.0f / (1.0f + __expf(-x)); }
__device__ __forceinline__ float tanhx(float x) { return 1.0f - 2.0f / (__expf(2.0f * x) + 1.0f); }

// ---------------------------------------------------------------------------
// Kernel 0: Wx^T in fp16:  g_wxTh[n][k] = half(Wx[k][n])
// ---------------------------------------------------------------------------
__global__ void wtrans(const float* __restrict__ w) {
    const int idx = blockIdx.x * 256 + threadIdx.x;   // over 256*512
    const int n = idx >> 9, k = idx & 511;
    g_wxTh[idx] = __float2half(w[(size_t)k * GDIM + n]);
}

// ---------------------------------------------------------------------------
// Kernel 1: xg[36864,256] = x @ Wx + bias  (fp16 mma m16n8k16, fp32 accum)
// BM=128, BN=256, BK=32. 512 threads = 16 warps (4m x 4n), warp tile 32x64.
// Double-buffered smem, one __syncthreads per K-tile.
// ---------------------------------------------------------------------------
#define BMg 128
#define BNg 256
#define BKg 32
#define KST 20                                   // half2 stride per row
#define STAGE ((BMg + BNg) * KST)                // 7680 unsigned per stage
#define GEMM_SMEM (2 * STAGE * 4)                // 61440 B

__global__ void __launch_bounds__(512, 1)
gemm_xg(const float* __restrict__ x, const float* __restrict__ bias) {
    extern __shared__ unsigned sm[];

    const int tid = threadIdx.x;
    const int bm  = blockIdx.x * BMg;
    const int wid = tid >> 5, lane = tid & 31;
    const int wm = wid & 3, wn = wid >> 2;
    const int grp = lane >> 2, tig = lane & 3;

    const int ra = tid >> 2, ca = (tid & 3) * 8;   // A: 8 floats / thread
    const int rb = tid >> 1, cb = (tid & 1) * 8;   // B: 8 half2 / thread

    const float* asrc = x + (size_t)(bm + ra) * DIM + ca;
    const __half* bsrc = g_wxTh + (size_t)rb * DIM + cb * 2;

    float4 av0, av1;
    uint4  bv0, bv1;

    auto LOAD = [&](int kt) {
        av0 = *(const float4*)(asrc + kt * BKg);
        av1 = *(const float4*)(asrc + kt * BKg + 4);
        bv0 = *(const uint4*)(bsrc + kt * BKg);
        bv1 = *(const uint4*)(bsrc + kt * BKg + 8);
    };
    auto STORE = [&](int s) {
        unsigned* As2 = sm + s * STAGE;
        unsigned* Bs2 = As2 + BMg * KST;
        uint4 ah;
        ah.x = pack_h2(av0.x, av0.y);
        ah.y = pack_h2(av0.z, av0.w);
        ah.z = pack_h2(av1.x, av1.y);
        ah.w = pack_h2(av1.z, av1.w);
        *(uint4*)(As2 + ra * KST + ca / 2)   = ah;
        *(uint4*)(Bs2 + rb * KST + cb)       = bv0;
        *(uint4*)(Bs2 + rb * KST + cb + 4)   = bv1;
    };

    float acc[2][8][4];
    #pragma unroll
    for (int i = 0; i < 2; i++)
        #pragma unroll
        for (int j = 0; j < 8; j++)
            #pragma unroll
            for (int k = 0; k < 4; k++) acc[i][j][k] = 0.0f;

    auto COMPUTE = [&](int s) {
        const unsigned* As2 = sm + s * STAGE;
        const unsigned* Bs2 = As2 + BMg * KST;
        #pragma unroll
        for (int ks = 0; ks < 2; ks++) {
            const int kb = ks * 8;
            unsigned af[2][4];
            #pragma unroll
            for (int mi = 0; mi < 2; mi++) {
                const int r0 = wm * 32 + mi * 16;
                af[mi][0] = As2[(r0 + grp) * KST + kb + tig];
                af[mi][1] = As2[(r0 + grp + 8) * KST + kb + tig];
                af[mi][2] = As2[(r0 + grp) * KST + kb + tig + 4];
                af[mi][3] = As2[(r0 + grp + 8) * KST + kb + tig + 4];
            }
            #pragma unroll
            for (int ni = 0; ni < 8; ni++) {
                const int c0 = wn * 64 + ni * 8;
                unsigned b0 = Bs2[(c0 + grp) * KST + kb + tig];
                unsigned b1 = Bs2[(c0 + grp) * KST + kb + tig + 4];
                #pragma unroll
                for (int mi = 0; mi < 2; mi++)
                    mma_f16(acc[mi][ni], af[mi][0], af[mi][1], af[mi][2], af[mi][3], b0, b1);
            }
        }
    };

    LOAD(0);
    STORE(0);
    __syncthreads();
    #pragma unroll 1
    for (int kt = 1; kt < DIM / BKg; kt++) {
        LOAD(kt);
        COMPUTE((kt - 1) & 1);
        STORE(kt & 1);
        __syncthreads();
    }
    COMPUTE(1);

    #pragma unroll
    for (int mi = 0; mi < 2; mi++) {
        #pragma unroll
        for (int ni = 0; ni < 8; ni++) {
            const int row = bm + wm * 32 + mi * 16 + grp;
            const int col = wn * 64 + ni * 8 + tig * 2;
            const float bb0 = bias[col], bb1 = bias[col + 1];
            g_xg[(size_t)row * GDIM + col]           = acc[mi][ni][0] + bb0;
            g_xg[(size_t)row * GDIM + col + 1]       = acc[mi][ni][1] + bb1;
            g_xg[(size_t)(row + 8) * GDIM + col]     = acc[mi][ni][2] + bb0;
            g_xg[(size_t)(row + 8) * GDIM + col + 1] = acc[mi][ni][3] + bb1;
        }
    }
}

// ---------------------------------------------------------------------------
// Kernel 2: TENSOR-CORE LSTM scan.
// CTA = 256 threads (8 warps), 16 batches. gates[16,256] = xg + h@Wh as ONE
// m16-tile of m16n8k16 mma: warp wn owns n-slice of 32 cols -> 4 ni x 4 kc
// = 16 mma/step. Wh B-fragments are TIME-INVARIANT: preloaded into 32 regs
// per warp (zero per-step weight traffic). Accumulators init from xg
// (prefetched 1 step ahead -> DRAM latency hidden under mma+activations).
// h round-trips via fp16 smem tile with stride-36 padding (4*l4+l2 bank
// bijection -> conflict-free fragment loads). 2 barriers/step.
// t=0 skips the mma (h0 = 0).
// ---------------------------------------------------------------------------
#define SC_NB 16
#define WS2 36                     // half2 stride per Wh row (4*l4+l2 bijection)
#define HS2 36                     // half2 stride per h row
#define GST 264                    // float stride per gates row
#define SCAN_SMEM (256 * WS2 * 4 + SC_NB * HS2 * 4 + SC_NB * GST * 4)  // 56064 B

__global__ void __launch_bounds__(256, 2)
lstm_scan(const float* __restrict__ w, float* __restrict__ out) {
    extern __shared__ unsigned smu[];
    unsigned* Whs = smu;                          // [256][WS2] half2
    unsigned* hs2 = smu + 256 * WS2;              // [16][HS2] half2
    float*    gmat = (float*)(smu + 256 * WS2 + SC_NB * HS2);  // [16][GST]

    const int tid  = threadIdx.x;
    const int lane = tid & 31;
    const int wn   = tid >> 5;          // warp -> n-slice (8 x 32 cols)
    const int l4   = lane >> 2;         // 0..7
    const int l2   = lane & 3;          // 0..3
    const int h    = tid & 63;          // gather id: hidden unit
    const int bq   = tid >> 6;          // gather id: batch quad
    const int bbase = blockIdx.x * SC_NB;

    // ---- fill Wh fp16 smem: Whs[n][k] = half(Wh[k][n]) ----
    for (int idx = tid; idx < 64 * 256; idx += 256) {
        const int k = idx >> 8, n = idx & 255;     // coalesced over n
        ((__half*)Whs)[n * (2 * WS2) + k] = __float2half(w[(size_t)(DIM + k) * GDIM + n]);
    }
    __syncthreads();

    // ---- preload constant B fragments: bf[kc][ni][2] ----
    unsigned bf[4][4][2];
    #pragma unroll
    for (int kc = 0; kc < 4; kc++)
        #pragma unroll
        for (int ni = 0; ni < 4; ni++) {
            const int col = wn * 32 + ni * 8 + l4;
            bf[kc][ni][0] = Whs[col * WS2 + kc * 8 + l2];
            bf[kc][ni][1] = Whs[col * WS2 + kc * 8 + l2 + 4];
        }

    float c[4];
    #pragma unroll
    for (int j = 0; j < 4; j++) c[j] = 0.0f;

    // xg prefetch buffer: [ni][{c0,c1,c2,c3}] fragment layout
    float pre[4][4];
    auto PREF = [&](int t) {
        #pragma unroll
        for (int ni = 0; ni < 4; ni++) {
            const int col = wn * 32 + ni * 8 + 2 * l2;
            const float2 v0 = *(const float2*)(g_xg +
                ((size_t)(bbase + l4) * TSTEPS + t) * GDIM + col);
            const float2 v1 = *(const float2*)(g_xg +
                ((size_t)(bbase + l4 + 8) * TSTEPS + t) * GDIM + col);
            pre[ni][0] = v0.x; pre[ni][1] = v0.y;
            pre[ni][2] = v1.x; pre[ni][3] = v1.y;
        }
    };

    PREF(0);

    #pragma unroll 1
    for (int t = 0; t < TSTEPS; t++) {
        // accumulators start at xg
        float acc[4][4];
        #pragma unroll
        for (int ni = 0; ni < 4; ni++)
            #pragma unroll
            for (int q = 0; q < 4; q++) acc[ni][q] = pre[ni][q];

        if (t + 1 < TSTEPS) PREF(t + 1);     // hide next step's xg latency

        if (t > 0) {
            // gates += h_{t-1} @ Wh  (tensor cores)
            #pragma unroll
            for (int kc = 0; kc < 4; kc++) {
                const unsigned a0 = hs2[l4 * HS2 + kc * 8 + l2];
                const unsigned a1 = hs2[(l4 + 8) * HS2 + kc * 8 + l2];
                const unsigned a2 = hs2[l4 * HS2 + kc * 8 + l2 + 4];
                const unsigned a3 = hs2[(l4 + 8) * HS2 + kc * 8 + l2 + 4];
                #pragma unroll
                for (int ni = 0; ni < 4; ni++)
                    mma_f16(acc[ni], a0, a1, a2, a3, bf[kc][ni][0], bf[kc][ni][1]);
            }
        }

        // scatter gates to smem in natural [batch][col] layout
        #pragma unroll
        for (int ni = 0; ni < 4; ni++) {
            const int col = wn * 32 + ni * 8 + 2 * l2;
            *(float2*)(gmat + l4 * GST + col)       = make_float2(acc[ni][0], acc[ni][1]);
            *(float2*)(gmat + (l4 + 8) * GST + col) = make_float2(acc[ni][2], acc[ni][3]);
        }
        __syncthreads();

        // gather quads + activations + state update + h fp16 writeback
        #pragma unroll
        for (int j = 0; j < 4; j++) {
            const int b = bq * 4 + j;
            const float gi = gmat[b * GST + h];
            const float gj = gmat[b * GST + 64 + h];
            const float gf = gmat[b * GST + 128 + h];
            const float go = gmat[b * GST + 192 + h];

            const float ig = sigm(gi);
            const float jg = tanhx(gj);
            const float fg = sigm(gf + 1.0f);        // FORGET_BIAS
            const float og = sigm(go);
            const float cn = fg * c[j] + ig * jg;
            c[j] = cn;
            const float hn = og * tanhx(cn);

            ((__half*)hs2)[b * (2 * HS2) + h] = __float2half(hn);
            out[((size_t)(bbase + b) * TSTEPS + t) * HIDDEN + h] = hn;
        }
        __syncthreads();
    }
}

// ---------------------------------------------------------------------------
extern "C" void kernel_launch(void* const* d_in, const int* in_sizes, int n_in,
                              void* d_out, int out_size) {
    const float* x    = (const float*)d_in[0];
    const float* w    = (const float*)d_in[1];
    const float* bias = (const float*)d_in[2];
    float* out        = (float*)d_out;
    (void)in_sizes; (void)n_in; (void)out_size;

    wtrans<<<GDIM * DIM / 256, 256>>>(w);

    cudaFuncSetAttribute(gemm_xg, cudaFuncAttributeMaxDynamicSharedMemorySize, GEMM_SMEM);
    gemm_xg<<<MROWS / BMg, 512, GEMM_SMEM>>>(x, bias);

    cudaFuncSetAttribute(lstm_scan, cudaFuncAttributeMaxDynamicSharedMemorySize, SCAN_SMEM);
    lstm_scan<<<BATCH / SC_NB, 256, SCAN_SMEM>>>(w, out);
}

// round 15
// speedup vs baseline: 1.3873x; 1.0394x over previous
#include <cuda_runtime.h>
#include <cuda_fp16.h>
#include <cstdint>

#define HIDDEN 64
#define BATCH  4096
#define TSTEPS 9
#define DIM    512
#define GDIM   256                 // 4*HIDDEN
#define MROWS  (BATCH * TSTEPS)    // 36864

// Scratch (static device globals: allocation-guard-safe)
__device__ float  g_xg[(size_t)MROWS * GDIM];   // xg = x @ Wx + bias
__device__ __half g_wxTh[(size_t)GDIM * DIM];   // Wx^T [256][512] in fp16

// ---------------------------------------------------------------------------
// helpers
// ---------------------------------------------------------------------------
__device__ __forceinline__ void mma_f16(float c[4],
                                        unsigned a0, unsigned a1, unsigned a2, unsigned a3,
                                        unsigned b0, unsigned b1) {
    asm volatile(
        "mma.sync.aligned.m16n8k16.row.col.f32.f16.f16.f32 "
        "{%0,%1,%2,%3}, {%4,%5,%6,%7}, {%8,%9}, {%0,%1,%2,%3};"
        : "+f"(c[0]), "+f"(c[1]), "+f"(c[2]), "+f"(c[3])
        : "r"(a0), "r"(a1), "r"(a2), "r"(a3), "r"(b0), "r"(b1));
}

__device__ __forceinline__ void ldm_x4(unsigned& r0, unsigned& r1,
                                       unsigned& r2, unsigned& r3, unsigned addr) {
    asm volatile("ldmatrix.sync.aligned.m8n8.x4.shared.b16 {%0,%1,%2,%3}, [%4];"
                 : "=r"(r0), "=r"(r1), "=r"(r2), "=r"(r3) : "r"(addr));
}

__device__ __forceinline__ uint32_t smem_u32(const void* p) {
    uint32_t a;
    asm("{ .reg .u64 t; cvta.to.shared.u64 t, %1; cvt.u32.u64 %0, t; }"
        : "=r"(a) : "l"(p));
    return a;
}

__device__ __forceinline__ unsigned pack_h2(float lo, float hi) {
    unsigned r;   // cvt.rn.f16x2.f32 d,a,b : a -> high half, b -> low half
    asm("cvt.rn.f16x2.f32 %0, %1, %2;" : "=r"(r) : "f"(hi), "f"(lo));
    return r;
}

__device__ __forceinline__ float sigm(float x)  { return 1.0f / (1.0f + __expf(-x)); }
__device__ __forceinline__ float tanhx(float x) { return 1.0f - 2.0f / (__expf(2.0f * x) + 1.0f); }

// ---------------------------------------------------------------------------
// Kernel 0: Wx^T in fp16:  g_wxTh[n][k] = half(Wx[k][n])
// ---------------------------------------------------------------------------
__global__ void wtrans(const float* __restrict__ w) {
    const int idx = blockIdx.x * 256 + threadIdx.x;   // over 256*512
    const int n = idx >> 9, k = idx & 511;
    g_wxTh[idx] = __float2half(w[(size_t)k * GDIM + n]);
}

// ---------------------------------------------------------------------------
// Kernel 1: xg[36864,256] = x @ Wx + bias  (fp16 mma m16n8k16, fp32 accum)
// BM=128, BN=256, BK=32. 512 threads = 16 warps (4m x 4n), warp tile 32x64.
// Double-buffered smem, one __syncthreads per K-tile. Fragment loads via
// ldmatrix.x4: 12 instr/warp/K-tile replaces 48 scalar LDS (was LDS-bound).
// Rows at 80B stride -> ldmatrix 8-row phases hit distinct banks.
// ---------------------------------------------------------------------------
#define BMg 128
#define BNg 256
#define BKg 32
#define KST 20                                   // half2 stride per row
#define STAGE ((BMg + BNg) * KST)                // 7680 unsigned per stage
#define GEMM_SMEM (2 * STAGE * 4)                // 61440 B

__global__ void __launch_bounds__(512, 1)
gemm_xg(const float* __restrict__ x, const float* __restrict__ bias) {
    extern __shared__ unsigned sm[];
    const uint32_t smb = smem_u32(sm);

    const int tid = threadIdx.x;
    const int bm  = blockIdx.x * BMg;
    const int wid = tid >> 5, lane = tid & 31;
    const int wm = wid & 3, wn = wid >> 2;
    const int lm = lane >> 3;          // ldmatrix matrix id 0..3
    const int lr = lane & 7;           // ldmatrix row-in-matrix

    const int ra = tid >> 2, ca = (tid & 3) * 8;   // A: 8 floats / thread
    const int rb = tid >> 1, cb = (tid & 1) * 8;   // B: 8 half2 / thread

    const float* asrc = x + (size_t)(bm + ra) * DIM + ca;
    const __half* bsrc = g_wxTh + (size_t)rb * DIM + cb * 2;

    float4 av0, av1;
    uint4  bv0, bv1;

    auto LOAD = [&](int kt) {
        av0 = *(const float4*)(asrc + kt * BKg);
        av1 = *(const float4*)(asrc + kt * BKg + 4);
        bv0 = *(const uint4*)(bsrc + kt * BKg);
        bv1 = *(const uint4*)(bsrc + kt * BKg + 8);
    };
    auto STORE = [&](int s) {
        unsigned* As2 = sm + s * STAGE;
        unsigned* Bs2 = As2 + BMg * KST;
        uint4 ah;
        ah.x = pack_h2(av0.x, av0.y);
        ah.y = pack_h2(av0.z, av0.w);
        ah.z = pack_h2(av1.x, av1.y);
        ah.w = pack_h2(av1.z, av1.w);
        *(uint4*)(As2 + ra * KST + ca / 2)   = ah;
        *(uint4*)(Bs2 + rb * KST + cb)       = bv0;
        *(uint4*)(Bs2 + rb * KST + cb + 4)   = bv1;
    };

    float acc[2][8][4];
    #pragma unroll
    for (int i = 0; i < 2; i++)
        #pragma unroll
        for (int j = 0; j < 8; j++)
            #pragma unroll
            for (int k = 0; k < 4; k++) acc[i][j][k] = 0.0f;

    // per-lane ldmatrix base offsets (bytes)
    //   A matrix m: row = wm*32 + mi*16 + (m&1)*8 + lr ; k-halves ofs (m>>1)*8
    //   B matrices (per np): m -> ni = 2np+(m>>1), k-halves ofs (m&1)*8
    const uint32_t a_lane_off = (uint32_t)(wm * 32 + (lm & 1) * 8 + lr) * (KST * 4)
                              + (uint32_t)(lm >> 1) * 16;
    const uint32_t b_lane_off = (uint32_t)(BMg * KST * 4)
                              + (uint32_t)(wn * 64 + (lm >> 1) * 8 + lr) * (KST * 4)
                              + (uint32_t)(lm & 1) * 16;

    auto COMPUTE = [&](int s) {
        const uint32_t sb = smb + (uint32_t)s * (STAGE * 4);
        #pragma unroll
        for (int ks = 0; ks < 2; ks++) {
            const uint32_t kofs = (uint32_t)ks * 32;   // 16 halves = 32 B
            unsigned af[2][4];
            #pragma unroll
            for (int mi = 0; mi < 2; mi++)
                ldm_x4(af[mi][0], af[mi][1], af[mi][2], af[mi][3],
                       sb + a_lane_off + (uint32_t)mi * 16 * (KST * 4) + kofs);
            unsigned bf[8][2];
            #pragma unroll
            for (int np = 0; np < 4; np++)
                ldm_x4(bf[2 * np][0], bf[2 * np][1], bf[2 * np + 1][0], bf[2 * np + 1][1],
                       sb + b_lane_off + (uint32_t)np * 16 * (KST * 4) + kofs);
            #pragma unroll
            for (int ni = 0; ni < 8; ni++)
                #pragma unroll
                for (int mi = 0; mi < 2; mi++)
                    mma_f16(acc[mi][ni], af[mi][0], af[mi][1], af[mi][2], af[mi][3],
                            bf[ni][0], bf[ni][1]);
        }
    };

    LOAD(0);
    STORE(0);
    __syncthreads();
    #pragma unroll 1
    for (int kt = 1; kt < DIM / BKg; kt++) {
        LOAD(kt);                    // prefetch hides under COMPUTE
        COMPUTE((kt - 1) & 1);
        STORE(kt & 1);               // safe: last read in iter kt-1, pre-barrier
        __syncthreads();             // single barrier per K-tile
    }
    COMPUTE(1);

    // epilogue: natural layout xg[row][col] + bias
    const int grp = lane >> 2, tig = lane & 3;
    #pragma unroll
    for (int mi = 0; mi < 2; mi++) {
        #pragma unroll
        for (int ni = 0; ni < 8; ni++) {
            const int row = bm + wm * 32 + mi * 16 + grp;
            const int col = wn * 64 + ni * 8 + tig * 2;
            const float bb0 = bias[col], bb1 = bias[col + 1];
            g_xg[(size_t)row * GDIM + col]           = acc[mi][ni][0] + bb0;
            g_xg[(size_t)row * GDIM + col + 1]       = acc[mi][ni][1] + bb1;
            g_xg[(size_t)(row + 8) * GDIM + col]     = acc[mi][ni][2] + bb0;
            g_xg[(size_t)(row + 8) * GDIM + col + 1] = acc[mi][ni][3] + bb1;
        }
    }
}

// ---------------------------------------------------------------------------
// Kernel 2: TENSOR-CORE LSTM scan (round-14 WIN — unchanged).
// CTA = 256 threads (8 warps), 16 batches; gates[16,256] = xg + h@Wh as one
// m16 tile; Wh B-fragments time-invariant in registers; xg prefetched one
// step ahead; h via fp16 smem, stride-36 bank bijection. t=0 skips mma.
// ---------------------------------------------------------------------------
#define SC_NB 16
#define WS2 36
#define HS2 36
#define GST 264
#define SCAN_SMEM (256 * WS2 * 4 + SC_NB * HS2 * 4 + SC_NB * GST * 4)  // 56064 B

__global__ void __launch_bounds__(256, 2)
lstm_scan(const float* __restrict__ w, float* __restrict__ out) {
    extern __shared__ unsigned smu[];
    unsigned* Whs = smu;                          // [256][WS2] half2
    unsigned* hs2 = smu + 256 * WS2;              // [16][HS2] half2
    float*    gmat = (float*)(smu + 256 * WS2 + SC_NB * HS2);  // [16][GST]

    const int tid  = threadIdx.x;
    const int lane = tid & 31;
    const int wn   = tid >> 5;
    const int l4   = lane >> 2;
    const int l2   = lane & 3;
    const int h    = tid & 63;
    const int bq   = tid >> 6;
    const int bbase = blockIdx.x * SC_NB;

    for (int idx = tid; idx < 64 * 256; idx += 256) {
        const int k = idx >> 8, n = idx & 255;
        ((__half*)Whs)[n * (2 * WS2) + k] = __float2half(w[(size_t)(DIM + k) * GDIM + n]);
    }
    __syncthreads();

    unsigned bf[4][4][2];
    #pragma unroll
    for (int kc = 0; kc < 4; kc++)
        #pragma unroll
        for (int ni = 0; ni < 4; ni++) {
            const int col = wn * 32 + ni * 8 + l4;
            bf[kc][ni][0] = Whs[col * WS2 + kc * 8 + l2];
            bf[kc][ni][1] = Whs[col * WS2 + kc * 8 + l2 + 4];
        }

    float c[4];
    #pragma unroll
    for (int j = 0; j < 4; j++) c[j] = 0.0f;

    float pre[4][4];
    auto PREF = [&](int t) {
        #pragma unroll
        for (int ni = 0; ni < 4; ni++) {
            const int col = wn * 32 + ni * 8 + 2 * l2;
            const float2 v0 = *(const float2*)(g_xg +
                ((size_t)(bbase + l4) * TSTEPS + t) * GDIM + col);
            const float2 v1 = *(const float2*)(g_xg +
                ((size_t)(bbase + l4 + 8) * TSTEPS + t) * GDIM + col);
            pre[ni][0] = v0.x; pre[ni][1] = v0.y;
            pre[ni][2] = v1.x; pre[ni][3] = v1.y;
        }
    };

    PREF(0);

    #pragma unroll 1
    for (int t = 0; t < TSTEPS; t++) {
        float acc[4][4];
        #pragma unroll
        for (int ni = 0; ni < 4; ni++)
            #pragma unroll
            for (int q = 0; q < 4; q++) acc[ni][q] = pre[ni][q];

        if (t + 1 < TSTEPS) PREF(t + 1);

        if (t > 0) {
            #pragma unroll
            for (int kc = 0; kc < 4; kc++) {
                const unsigned a0 = hs2[l4 * HS2 + kc * 8 + l2];
                const unsigned a1 = hs2[(l4 + 8) * HS2 + kc * 8 + l2];
                const unsigned a2 = hs2[l4 * HS2 + kc * 8 + l2 + 4];
                const unsigned a3 = hs2[(l4 + 8) * HS2 + kc * 8 + l2 + 4];
                #pragma unroll
                for (int ni = 0; ni < 4; ni++)
                    mma_f16(acc[ni], a0, a1, a2, a3, bf[kc][ni][0], bf[kc][ni][1]);
            }
        }

        #pragma unroll
        for (int ni = 0; ni < 4; ni++) {
            const int col = wn * 32 + ni * 8 + 2 * l2;
            *(float2*)(gmat + l4 * GST + col)       = make_float2(acc[ni][0], acc[ni][1]);
            *(float2*)(gmat + (l4 + 8) * GST + col) = make_float2(acc[ni][2], acc[ni][3]);
        }
        __syncthreads();

        #pragma unroll
        for (int j = 0; j < 4; j++) {
            const int b = bq * 4 + j;
            const float gi = gmat[b * GST + h];
            const float gj = gmat[b * GST + 64 + h];
            const float gf = gmat[b * GST + 128 + h];
            const float go = gmat[b * GST + 192 + h];

            const float ig = sigm(gi);
            const float jg = tanhx(gj);
            const float fg = sigm(gf + 1.0f);        // FORGET_BIAS
            const float og = sigm(go);
            const float cn = fg * c[j] + ig * jg;
            c[j] = cn;
            const float hn = og * tanhx(cn);

            ((__half*)hs2)[b * (2 * HS2) + h] = __float2half(hn);
            out[((size_t)(bbase + b) * TSTEPS + t) * HIDDEN + h] = hn;
        }
        __syncthreads();
    }
}

// ---------------------------------------------------------------------------
extern "C" void kernel_launch(void* const* d_in, const int* in_sizes, int n_in,
                              void* d_out, int out_size) {
    const float* x    = (const float*)d_in[0];
    const float* w    = (const float*)d_in[1];
    const float* bias = (const float*)d_in[2];
    float* out        = (float*)d_out;
    (void)in_sizes; (void)n_in; (void)out_size;

    wtrans<<<GDIM * DIM / 256, 256>>>(w);

    cudaFuncSetAttribute(gemm_xg, cudaFuncAttributeMaxDynamicSharedMemorySize, GEMM_SMEM);
    gemm_xg<<<MROWS / BMg, 512, GEMM_SMEM>>>(x, bias);

    cudaFuncSetAttribute(lstm_scan, cudaFuncAttributeMaxDynamicSharedMemorySize, SCAN_SMEM);
    lstm_scan<<<BATCH / SC_NB, 256, SCAN_SMEM>>>(w, out);
}